// round 14
// baseline (speedup 1.0000x reference)
#include <cuda_runtime.h>

static constexpr int B = 64;
static constexpr int N = 512 * 512;          // 262144 floats per row
static constexpr int N4 = N / 4;             // 65536 float4 per row
static constexpr int BLOCKS_PER_ROW = 32;
static constexpr int THREADS = 256;
static constexpr int VEC_PER_THREAD = N4 / (BLOCKS_PER_ROW * THREADS); // 8
static constexpr int NPART = B * BLOCKS_PER_ROW;                      // 2048

// Scratch: per-block partials, fully overwritten each launch (no init needed).
__device__ float g_part_ps[NPART];
__device__ float g_part_ts[NPART];
__device__ float g_part_in[NPART];
__device__ unsigned int g_done_count = 0;   // reset to 0 by the last block

__device__ __forceinline__ float4 ldcs4(const float4* p) {
    return __ldcs(p);
}

__global__ __launch_bounds__(THREADS) void dice_fused_kernel(
    const float* __restrict__ pred, const float* __restrict__ target,
    float* __restrict__ out)
{
    const int row = blockIdx.y;
    const long long row_base = (long long)row * N4;
    const int chunk = blockIdx.x * (THREADS * VEC_PER_THREAD) + threadIdx.x;

    const float4* __restrict__ p4 = reinterpret_cast<const float4*>(pred) + row_base;
    const float4* __restrict__ t4 = reinterpret_cast<const float4*>(target) + row_base;

    float ps = 0.f, ts = 0.f, in = 0.f;
#pragma unroll
    for (int v = 0; v < VEC_PER_THREAD; v++) {
        const int idx = chunk + v * THREADS;   // coalesced, stride THREADS
        float4 p = ldcs4(&p4[idx]);
        float4 t = ldcs4(&t4[idx]);
        ps += (p.x + p.y) + (p.z + p.w);
        ts += (t.x + t.y) + (t.z + t.w);
        in += p.x * t.x + p.y * t.y + p.z * t.z + p.w * t.w;
    }

    // warp reduce
#pragma unroll
    for (int off = 16; off > 0; off >>= 1) {
        ps += __shfl_down_sync(0xffffffffu, ps, off);
        ts += __shfl_down_sync(0xffffffffu, ts, off);
        in += __shfl_down_sync(0xffffffffu, in, off);
    }

    __shared__ float s_ps[THREADS / 32];
    __shared__ float s_ts[THREADS / 32];
    __shared__ float s_in[THREADS / 32];
    __shared__ bool  s_is_last;
    const int lane = threadIdx.x & 31;
    const int wid  = threadIdx.x >> 5;
    if (lane == 0) { s_ps[wid] = ps; s_ts[wid] = ts; s_in[wid] = in; }
    __syncthreads();

    if (threadIdx.x == 0) {
        float bps = 0.f, bts = 0.f, bin = 0.f;
#pragma unroll
        for (int w = 0; w < THREADS / 32; w++) {
            bps += s_ps[w]; bts += s_ts[w]; bin += s_in[w];
        }
        const int slot = row * BLOCKS_PER_ROW + blockIdx.x;
        g_part_ps[slot] = bps;
        g_part_ts[slot] = bts;
        g_part_in[slot] = bin;
        __threadfence();                               // publish partials
        unsigned int old = atomicAdd(&g_done_count, 1u);
        s_is_last = (old == NPART - 1);
    }
    __syncthreads();

    if (!s_is_last) return;

    // ---- Last block: reduce 2048 partials per quantity + epilogue ----
    __threadfence();                                   // acquire
    const float SMOOTH = 1.0f;
    __shared__ float s_loss[B];

    // 8 warps; warp w handles rows w, w+8, ..., w+56 (8 rows each).
    // Each row's 32 partials map to 32 lanes -> one shuffle reduce.
#pragma unroll
    for (int i = 0; i < B / (THREADS / 32); i++) {
        const int r = wid + i * (THREADS / 32);
        const int slot = r * BLOCKS_PER_ROW + lane;
        float rps = g_part_ps[slot];
        float rts = g_part_ts[slot];
        float rin = g_part_in[slot];
#pragma unroll
        for (int off = 16; off > 0; off >>= 1) {
            rps += __shfl_down_sync(0xffffffffu, rps, off);
            rts += __shfl_down_sync(0xffffffffu, rts, off);
            rin += __shfl_down_sync(0xffffffffu, rin, off);
        }
        if (lane == 0) {
            float dice_loss = 1.0f - (2.0f * rin + SMOOTH) / (rps + rts + SMOOTH);
            float zero_loss = rps / (float)N;
            s_loss[r] = (rts == 0.0f) ? zero_loss : dice_loss;
        }
    }
    __syncthreads();

    // Reduce 64 losses -> mean (warps 0 and 1), then write scalar + reset counter.
    if (wid < 2) {
        float v = s_loss[wid * 32 + lane];
#pragma unroll
        for (int off = 16; off > 0; off >>= 1)
            v += __shfl_down_sync(0xffffffffu, v, off);
        if (lane == 0) s_loss[wid] = v;   // reuse slots 0,1
    }
    __syncthreads();
    if (threadIdx.x == 0) {
        out[0] = (s_loss[0] + s_loss[1]) / (float)B;
        g_done_count = 0;                 // deterministic graph replay
    }
}

extern "C" void kernel_launch(void* const* d_in, const int* in_sizes, int n_in,
                              void* d_out, int out_size) {
    const float* pred   = (const float*)d_in[0];
    const float* target = (const float*)d_in[1];
    float* out = (float*)d_out;

    dim3 grid(BLOCKS_PER_ROW, B);
    dice_fused_kernel<<<grid, THREADS>>>(pred, target, out);
}